// round 12
// baseline (speedup 1.0000x reference)
#include <cuda_runtime.h>
#include <stdint.h>

#define N_NODES 65536
#define N_GRAPHS 32
#define NPG 2048
#define N_EDGES 1048576
#define F_IN 16
#define H1 64
#define H2 64
#define OUT_F 12
#define SLOTS 64   // padded CSR slots per node (max in-degree; Poisson(16))

typedef unsigned long long u64;

// ---------------- scratch (device globals: allocation-free) ----------------
__device__ int   g_counts[N_NODES];          // in-degree (derived from cursors)
__device__ int   g_cur[N_NODES];             // scatter cursors (init node*SLOTS)
__device__ int   g_csr[N_NODES * SLOTS];     // padded per-node src lists
__device__ float g_dinv[N_NODES];
__device__ float g_xs[(N_NODES + 1) * F_IN];   // +1 sentinel zero row
__device__ float g_aggx[N_NODES * F_IN];
__device__ float g_hs2[(N_NODES + 1) * H2];    // +1 sentinel zero row
__device__ float g_agg2[N_NODES * H2];

__device__ __forceinline__ float tanhx(float x) {
    float y;
    asm("tanh.approx.f32 %0, %1;" : "=f"(y) : "f"(x));
    return y;
}

__device__ __forceinline__ u64 pack2(float lo, float hi) {
    u64 r;
    asm("mov.b64 %0, {%1, %2};" : "=l"(r) : "f"(lo), "f"(hi));
    return r;
}

__device__ __forceinline__ void unpack2(float& lo, float& hi, u64 v) {
    asm("mov.b64 {%0, %1}, %2;" : "=f"(lo), "=f"(hi) : "l"(v));
}

__device__ __forceinline__ void fma2(u64& d, u64 a, u64 b) {
    asm("fma.rn.f32x2 %0, %1, %2, %3;" : "=l"(d) : "l"(a), "l"(b), "l"(d));
}

// ---------------- init: cursors + sentinel rows + out=bfc ------------------
__global__ void k_init(const float* __restrict__ bfc, float* __restrict__ out) {
    int i = blockIdx.x * blockDim.x + threadIdx.x;
    g_cur[i] = i * SLOTS;
    if (i < F_IN) g_xs[(size_t)N_NODES * F_IN + i] = 0.f;
    if (i < H2)   g_hs2[(size_t)N_NODES * H2 + i] = 0.f;
    if (i < N_GRAPHS * OUT_F) out[i] = __ldg(&bfc[i % OUT_F]);
}

// ---------------- scatter: 4 edges/thread, builds padded CSR ---------------
__global__ void __launch_bounds__(256) k_scatter(const int* __restrict__ src,
                                                 const int* __restrict__ dst) {
    int t = blockIdx.x * blockDim.x + threadIdx.x;
    int4 d = __ldg(reinterpret_cast<const int4*>(dst) + t);
    int4 s = __ldg(reinterpret_cast<const int4*>(src) + t);
    int p0 = atomicAdd(&g_cur[d.x], 1);
    int p1 = atomicAdd(&g_cur[d.y], 1);
    int p2 = atomicAdd(&g_cur[d.z], 1);
    int p3 = atomicAdd(&g_cur[d.w], 1);
    g_csr[p0] = s.x;
    g_csr[p1] = s.y;
    g_csr[p2] = s.z;
    g_csr[p3] = s.w;
}

// ---------------- finalize: counts, pad-to-4 sentinels, dinv, x prescale ---
__global__ void __launch_bounds__(256) k_xs(const float* __restrict__ x) {
    int i = blockIdx.x * blockDim.x + threadIdx.x;
    int base = i * SLOTS;
    int cnt = g_cur[i] - base;
    g_counts[i] = cnt;

    int end = (cnt + 3) & ~3;               // pad list to multiple of 4
    for (int j = cnt; j < end; j++) g_csr[base + j] = N_NODES;  // sentinel

    float dinv = rsqrtf((float)(cnt + 1));  // +1 self-loop
    g_dinv[i] = dinv;

    const float4* x4 = reinterpret_cast<const float4*>(x) + i * 4;
    float4* xs4 = reinterpret_cast<float4*>(g_xs) + i * 4;
#pragma unroll
    for (int k = 0; k < 4; k++) {
        float4 v = __ldg(&x4[k]);
        v.x *= dinv; v.y *= dinv; v.z *= dinv; v.w *= dinv;
        xs4[k] = v;
    }
}

// ---------------- layer-1 gather (16 dims, 4 lanes/node), int4 idx ---------
__global__ void __launch_bounds__(256) k_gather1() {
    unsigned tid = blockIdx.x * blockDim.x + threadIdx.x;
    unsigned node = tid >> 2;
    unsigned c = tid & 3u;
    const float4* hs = reinterpret_cast<const float4*>(g_xs);
    const int4* csr4 = reinterpret_cast<const int4*>(g_csr) + node * (SLOTS / 4);

    int iters = (__ldg(&g_counts[node]) + 3) >> 2;

    float4 acc = __ldg(&hs[(size_t)node * 4 + c]);  // self-loop

    for (int it = 0; it < iters; it++) {
        int4 idx = __ldg(&csr4[it]);
        float4 v0 = __ldg(&hs[(size_t)idx.x * 4 + c]);
        float4 v1 = __ldg(&hs[(size_t)idx.y * 4 + c]);
        float4 v2 = __ldg(&hs[(size_t)idx.z * 4 + c]);
        float4 v3 = __ldg(&hs[(size_t)idx.w * 4 + c]);
        acc.x += v0.x + v1.x + v2.x + v3.x;
        acc.y += v0.y + v1.y + v2.y + v3.y;
        acc.z += v0.z + v1.z + v2.z + v3.z;
        acc.w += v0.w + v1.w + v2.w + v3.w;
    }
    reinterpret_cast<float4*>(g_aggx)[(size_t)node * 4 + c] = acc;
}

// ---------------- fused node GEMMs: 16 -> tanh(64) -> 64 (f32x2 layer 2) ---
__global__ void __launch_bounds__(128) k_h12(const float* __restrict__ W1,
                                             const float* __restrict__ b1,
                                             const float* __restrict__ W2) {
    __shared__ float sW1[F_IN * H1];
    __shared__ alignas(16) float sW2[H1 * H2];
    __shared__ float sb1[H1];
    for (int i = threadIdx.x; i < F_IN * H1; i += blockDim.x) sW1[i] = W1[i];
    for (int i = threadIdx.x; i < H1 * H2; i += blockDim.x) sW2[i] = W2[i];
    if (threadIdx.x < H1) sb1[threadIdx.x] = b1[threadIdx.x];
    __syncthreads();

    int node = blockIdx.x * blockDim.x + threadIdx.x;
    float dinv = g_dinv[node];

    float xi[F_IN];
    const float4* a4 = reinterpret_cast<const float4*>(g_aggx) + node * 4;
#pragma unroll
    for (int k = 0; k < 4; k++) {
        float4 v = a4[k];
        xi[4 * k + 0] = v.x; xi[4 * k + 1] = v.y;
        xi[4 * k + 2] = v.z; xi[4 * k + 3] = v.w;
    }

    float t[H1];
#pragma unroll
    for (int j0 = 0; j0 < H1; j0 += 16) {
        float acc[16];
#pragma unroll
        for (int jj = 0; jj < 16; jj++) acc[jj] = 0.f;
#pragma unroll
        for (int k = 0; k < F_IN; k++) {
            float xv = xi[k];
#pragma unroll
            for (int jj = 0; jj < 16; jj++)
                acc[jj] = fmaf(xv, sW1[k * H1 + j0 + jj], acc[jj]);
        }
#pragma unroll
        for (int jj = 0; jj < 16; jj++)
            t[j0 + jj] = tanhx(fmaf(acc[jj], dinv, sb1[j0 + jj]));
    }

    // layer-2 GEMM in packed f32x2 (full fp32 precision, 2x FMA rate)
#pragma unroll
    for (int j0 = 0; j0 < H2; j0 += 16) {
        u64 acc2[8];
#pragma unroll
        for (int q = 0; q < 8; q++) acc2[q] = 0ull;  // (0.f, 0.f)
#pragma unroll
        for (int h = 0; h < H1; h++) {
            u64 tp = pack2(t[h], t[h]);
            const u64* wrow = reinterpret_cast<const u64*>(&sW2[h * H2 + j0]);
#pragma unroll
            for (int q = 0; q < 8; q++) fma2(acc2[q], tp, wrow[q]);
        }
#pragma unroll
        for (int q = 0; q < 8; q += 2) {
            float a0, a1, a2, a3;
            unpack2(a0, a1, acc2[q]);
            unpack2(a2, a3, acc2[q + 1]);
            float4 o = make_float4(a0 * dinv, a1 * dinv, a2 * dinv, a3 * dinv);
            reinterpret_cast<float4*>(g_hs2)[node * (H2 / 4) + ((j0 + 2 * q) >> 2)] = o;
        }
    }
}

// ---------------- layer-2 gather (64 dims, 16 lanes/node), int4 idx --------
__global__ void __launch_bounds__(256) k_gather2() {
    unsigned tid = blockIdx.x * blockDim.x + threadIdx.x;
    unsigned node = tid >> 4;
    unsigned c = tid & 15u;
    const float4* hs = reinterpret_cast<const float4*>(g_hs2);
    const int4* csr4 = reinterpret_cast<const int4*>(g_csr) + node * (SLOTS / 4);

    int iters = (__ldg(&g_counts[node]) + 3) >> 2;

    float4 acc = __ldg(&hs[(size_t)node * 16 + c]);  // self-loop

    for (int it = 0; it < iters; it++) {
        int4 idx = __ldg(&csr4[it]);
        float4 v0 = __ldg(&hs[(size_t)idx.x * 16 + c]);
        float4 v1 = __ldg(&hs[(size_t)idx.y * 16 + c]);
        float4 v2 = __ldg(&hs[(size_t)idx.z * 16 + c]);
        float4 v3 = __ldg(&hs[(size_t)idx.w * 16 + c]);
        acc.x += v0.x + v1.x + v2.x + v3.x;
        acc.y += v0.y + v1.y + v2.y + v3.y;
        acc.z += v0.z + v1.z + v2.z + v3.z;
        acc.w += v0.w + v1.w + v2.w + v3.w;
    }
    reinterpret_cast<float4*>(g_agg2)[(size_t)node * 16 + c] = acc;
}

// ---------------- fused tanh/FC (8 graphs/block) ---------------------------
#define FC_CHUNKS 64
#define FC_KC ((NPG * H2) / FC_CHUNKS)  // 2048 k-elements per chunk
#define FC_GPB 8                        // graphs per block (Wfc L2 reuse)

__global__ void __launch_bounds__(256) k_fc(const float* __restrict__ Wfc,
                                            const float* __restrict__ b2,
                                            float* __restrict__ out) {
    __shared__ float sred[8][OUT_F];
    int chunk = blockIdx.x & (FC_CHUNKS - 1);
    int ggrp  = blockIdx.x >> 6;  // 0..3
    int t = threadIdx.x;
    int lane = t & 31, warp = t >> 5;
    int kbase = chunk * FC_KC;

    for (int gg = 0; gg < FC_GPB; gg++) {
        int g = ggrp * FC_GPB + gg;
        float acc[OUT_F];
#pragma unroll
        for (int o = 0; o < OUT_F; o++) acc[o] = 0.f;

#pragma unroll
        for (int i = 0; i < FC_KC / 256; i++) {
            int k = kbase + i * 256 + t;            // [0, 131072)
            int n = g * NPG + (k >> 6);
            int h = k & 63;
            float v = tanhx(fmaf(__ldg(&g_agg2[(size_t)g * (NPG * H2) + k]),
                                 g_dinv[n], __ldg(&b2[h])));
            const float4* w4 = reinterpret_cast<const float4*>(Wfc + (size_t)k * OUT_F);
            float4 w0 = __ldg(&w4[0]);
            float4 w1 = __ldg(&w4[1]);
            float4 w2 = __ldg(&w4[2]);
            acc[0]  = fmaf(v, w0.x, acc[0]);
            acc[1]  = fmaf(v, w0.y, acc[1]);
            acc[2]  = fmaf(v, w0.z, acc[2]);
            acc[3]  = fmaf(v, w0.w, acc[3]);
            acc[4]  = fmaf(v, w1.x, acc[4]);
            acc[5]  = fmaf(v, w1.y, acc[5]);
            acc[6]  = fmaf(v, w1.z, acc[6]);
            acc[7]  = fmaf(v, w1.w, acc[7]);
            acc[8]  = fmaf(v, w2.x, acc[8]);
            acc[9]  = fmaf(v, w2.y, acc[9]);
            acc[10] = fmaf(v, w2.z, acc[10]);
            acc[11] = fmaf(v, w2.w, acc[11]);
        }

#pragma unroll
        for (int o = 0; o < OUT_F; o++) {
            float s = acc[o];
#pragma unroll
            for (int off = 16; off > 0; off >>= 1)
                s += __shfl_down_sync(0xffffffffu, s, off);
            if (lane == 0) sred[warp][o] = s;
        }
        __syncthreads();
        if (t < OUT_F) {
            float s = 0.f;
#pragma unroll
            for (int w = 0; w < 8; w++) s += sred[w][t];
            atomicAdd(&out[g * OUT_F + t], s);
        }
        __syncthreads();
    }
}

// ---------------- launcher -------------------------------------------------
extern "C" void kernel_launch(void* const* d_in, const int* in_sizes, int n_in,
                              void* d_out, int out_size) {
    (void)in_sizes; (void)n_in; (void)out_size;
    const float* x   = (const float*)d_in[0];
    const int*   ei  = (const int*)d_in[1];
    // d_in[2] = batch (unused: layout is a fixed reshape)
    const float* W1  = (const float*)d_in[3];
    const float* b1  = (const float*)d_in[4];
    const float* W2  = (const float*)d_in[5];
    const float* b2  = (const float*)d_in[6];
    const float* Wfc = (const float*)d_in[7];
    const float* bfc = (const float*)d_in[8];
    float* out = (float*)d_out;

    const int* src = ei;
    const int* dst = ei + N_EDGES;

    k_init<<<N_NODES / 256, 256>>>(bfc, out);
    k_scatter<<<N_EDGES / 4 / 256, 256>>>(src, dst);
    k_xs<<<N_NODES / 256, 256>>>(x);
    k_gather1<<<(N_NODES * 4) / 256, 256>>>();
    k_h12<<<N_NODES / 128, 128>>>(W1, b1, W2);
    k_gather2<<<(N_NODES * 16) / 256, 256>>>();
    k_fc<<<4 * FC_CHUNKS, 256>>>(Wfc, b2, out);
}

// round 13
// speedup vs baseline: 1.0175x; 1.0175x over previous
#include <cuda_runtime.h>
#include <stdint.h>

#define N_NODES 65536
#define N_GRAPHS 32
#define NPG 2048
#define N_EDGES 1048576
#define F_IN 16
#define H1 64
#define H2 64
#define OUT_F 12
#define SLOTS 64   // padded CSR slots per node (max in-degree; Poisson(16))

typedef unsigned long long u64;

// ---------------- scratch (device globals: allocation-free) ----------------
__device__ int   g_counts[N_NODES];          // in-degree (derived from cursors)
__device__ int   g_cur[N_NODES];             // scatter cursors (init node*SLOTS)
__device__ int   g_csr[N_NODES * SLOTS];     // padded per-node src lists
__device__ float g_dinv[N_NODES];
__device__ float g_xs[(N_NODES + 1) * F_IN];   // +1 sentinel zero row
__device__ float g_aggx[N_NODES * F_IN];
__device__ float g_hs2[(N_NODES + 1) * H2];    // +1 sentinel zero row
__device__ float g_agg2[N_NODES * H2];

__device__ __forceinline__ float tanhx(float x) {
    float y;
    asm("tanh.approx.f32 %0, %1;" : "=f"(y) : "f"(x));
    return y;
}

__device__ __forceinline__ u64 pack2(float lo, float hi) {
    u64 r;
    asm("mov.b64 %0, {%1, %2};" : "=l"(r) : "f"(lo), "f"(hi));
    return r;
}

__device__ __forceinline__ void unpack2(float& lo, float& hi, u64 v) {
    asm("mov.b64 {%0, %1}, %2;" : "=f"(lo), "=f"(hi) : "l"(v));
}

__device__ __forceinline__ void fma2(u64& d, u64 a, u64 b) {
    asm("fma.rn.f32x2 %0, %1, %2, %3;" : "=l"(d) : "l"(a), "l"(b), "l"(d));
}

// ---------------- init: cursors + sentinel rows + out=bfc ------------------
__global__ void k_init(const float* __restrict__ bfc, float* __restrict__ out) {
    int i = blockIdx.x * blockDim.x + threadIdx.x;
    g_cur[i] = i * SLOTS;
    if (i < F_IN) g_xs[(size_t)N_NODES * F_IN + i] = 0.f;
    if (i < H2)   g_hs2[(size_t)N_NODES * H2 + i] = 0.f;
    if (i < N_GRAPHS * OUT_F) out[i] = __ldg(&bfc[i % OUT_F]);
}

// ---------------- scatter: 4 edges/thread, builds padded CSR ---------------
__global__ void __launch_bounds__(256) k_scatter(const int* __restrict__ src,
                                                 const int* __restrict__ dst) {
    int t = blockIdx.x * blockDim.x + threadIdx.x;
    int4 d = __ldg(reinterpret_cast<const int4*>(dst) + t);
    int4 s = __ldg(reinterpret_cast<const int4*>(src) + t);
    int p0 = atomicAdd(&g_cur[d.x], 1);
    int p1 = atomicAdd(&g_cur[d.y], 1);
    int p2 = atomicAdd(&g_cur[d.z], 1);
    int p3 = atomicAdd(&g_cur[d.w], 1);
    g_csr[p0] = s.x;
    g_csr[p1] = s.y;
    g_csr[p2] = s.z;
    g_csr[p3] = s.w;
}

// ---------------- finalize: counts, pad-to-4 sentinels, dinv, x prescale ---
__global__ void __launch_bounds__(256) k_xs(const float* __restrict__ x) {
    int i = blockIdx.x * blockDim.x + threadIdx.x;
    int base = i * SLOTS;
    int cnt = g_cur[i] - base;
    g_counts[i] = cnt;

    int end = (cnt + 3) & ~3;               // pad list to multiple of 4
    for (int j = cnt; j < end; j++) g_csr[base + j] = N_NODES;  // sentinel

    float dinv = rsqrtf((float)(cnt + 1));  // +1 self-loop
    g_dinv[i] = dinv;

    const float4* x4 = reinterpret_cast<const float4*>(x) + i * 4;
    float4* xs4 = reinterpret_cast<float4*>(g_xs) + i * 4;
#pragma unroll
    for (int k = 0; k < 4; k++) {
        float4 v = __ldg(&x4[k]);
        v.x *= dinv; v.y *= dinv; v.z *= dinv; v.w *= dinv;
        xs4[k] = v;
    }
}

// ---------------- layer-1 gather (16 dims, 4 lanes/node) -------------------
__global__ void __launch_bounds__(256) k_gather1() {
    unsigned tid = blockIdx.x * blockDim.x + threadIdx.x;
    unsigned node = tid >> 2;
    unsigned c = tid & 3u;
    const float4* hs = reinterpret_cast<const float4*>(g_xs);

    int base = node * SLOTS;
    int iters = (__ldg(&g_counts[node]) + 3) >> 2;

    float4 acc = __ldg(&hs[(size_t)node * 4 + c]);  // self-loop

    for (int it = 0; it < iters; it++) {
        int j = base + it * 4;
        int s0 = __ldg(&g_csr[j + 0]);
        int s1 = __ldg(&g_csr[j + 1]);
        int s2 = __ldg(&g_csr[j + 2]);
        int s3 = __ldg(&g_csr[j + 3]);
        float4 v0 = __ldg(&hs[(size_t)s0 * 4 + c]);
        float4 v1 = __ldg(&hs[(size_t)s1 * 4 + c]);
        float4 v2 = __ldg(&hs[(size_t)s2 * 4 + c]);
        float4 v3 = __ldg(&hs[(size_t)s3 * 4 + c]);
        acc.x += v0.x + v1.x + v2.x + v3.x;
        acc.y += v0.y + v1.y + v2.y + v3.y;
        acc.z += v0.z + v1.z + v2.z + v3.z;
        acc.w += v0.w + v1.w + v2.w + v3.w;
    }
    reinterpret_cast<float4*>(g_aggx)[(size_t)node * 4 + c] = acc;
}

// ---------------- fused node GEMMs: 16 -> tanh(64) -> 64 (f32x2 both) ------
__global__ void __launch_bounds__(128) k_h12(const float* __restrict__ W1,
                                             const float* __restrict__ b1,
                                             const float* __restrict__ W2) {
    __shared__ alignas(16) float sW1[F_IN * H1];
    __shared__ alignas(16) float sW2[H1 * H2];
    __shared__ float sb1[H1];
    for (int i = threadIdx.x; i < F_IN * H1; i += blockDim.x) sW1[i] = W1[i];
    for (int i = threadIdx.x; i < H1 * H2; i += blockDim.x) sW2[i] = W2[i];
    if (threadIdx.x < H1) sb1[threadIdx.x] = b1[threadIdx.x];
    __syncthreads();

    int node = blockIdx.x * blockDim.x + threadIdx.x;
    float dinv = g_dinv[node];

    float xi[F_IN];
    const float4* a4 = reinterpret_cast<const float4*>(g_aggx) + node * 4;
#pragma unroll
    for (int k = 0; k < 4; k++) {
        float4 v = a4[k];
        xi[4 * k + 0] = v.x; xi[4 * k + 1] = v.y;
        xi[4 * k + 2] = v.z; xi[4 * k + 3] = v.w;
    }

    // layer-1 GEMM (f32x2) + tanh
    float t[H1];
#pragma unroll
    for (int j0 = 0; j0 < H1; j0 += 16) {
        u64 acc2[8];
#pragma unroll
        for (int q = 0; q < 8; q++) acc2[q] = 0ull;
#pragma unroll
        for (int k = 0; k < F_IN; k++) {
            u64 xp = pack2(xi[k], xi[k]);
            const u64* wrow = reinterpret_cast<const u64*>(&sW1[k * H1 + j0]);
#pragma unroll
            for (int q = 0; q < 8; q++) fma2(acc2[q], xp, wrow[q]);
        }
#pragma unroll
        for (int q = 0; q < 8; q++) {
            float a0, a1;
            unpack2(a0, a1, acc2[q]);
            t[j0 + 2 * q + 0] = tanhx(fmaf(a0, dinv, sb1[j0 + 2 * q + 0]));
            t[j0 + 2 * q + 1] = tanhx(fmaf(a1, dinv, sb1[j0 + 2 * q + 1]));
        }
    }

    // layer-2 GEMM (f32x2), prescale by dinv
#pragma unroll
    for (int j0 = 0; j0 < H2; j0 += 16) {
        u64 acc2[8];
#pragma unroll
        for (int q = 0; q < 8; q++) acc2[q] = 0ull;
#pragma unroll
        for (int h = 0; h < H1; h++) {
            u64 tp = pack2(t[h], t[h]);
            const u64* wrow = reinterpret_cast<const u64*>(&sW2[h * H2 + j0]);
#pragma unroll
            for (int q = 0; q < 8; q++) fma2(acc2[q], tp, wrow[q]);
        }
#pragma unroll
        for (int q = 0; q < 8; q += 2) {
            float a0, a1, a2, a3;
            unpack2(a0, a1, acc2[q]);
            unpack2(a2, a3, acc2[q + 1]);
            float4 o = make_float4(a0 * dinv, a1 * dinv, a2 * dinv, a3 * dinv);
            reinterpret_cast<float4*>(g_hs2)[node * (H2 / 4) + ((j0 + 2 * q) >> 2)] = o;
        }
    }
}

// ---------------- layer-2 gather (64 dims, 16 lanes/node) ------------------
__global__ void __launch_bounds__(256) k_gather2() {
    unsigned tid = blockIdx.x * blockDim.x + threadIdx.x;
    unsigned node = tid >> 4;
    unsigned c = tid & 15u;
    const float4* hs = reinterpret_cast<const float4*>(g_hs2);

    int base = node * SLOTS;
    int iters = (__ldg(&g_counts[node]) + 3) >> 2;

    float4 acc = __ldg(&hs[(size_t)node * 16 + c]);  // self-loop

    for (int it = 0; it < iters; it++) {
        int j = base + it * 4;
        int s0 = __ldg(&g_csr[j + 0]);
        int s1 = __ldg(&g_csr[j + 1]);
        int s2 = __ldg(&g_csr[j + 2]);
        int s3 = __ldg(&g_csr[j + 3]);
        float4 v0 = __ldg(&hs[(size_t)s0 * 16 + c]);
        float4 v1 = __ldg(&hs[(size_t)s1 * 16 + c]);
        float4 v2 = __ldg(&hs[(size_t)s2 * 16 + c]);
        float4 v3 = __ldg(&hs[(size_t)s3 * 16 + c]);
        acc.x += v0.x + v1.x + v2.x + v3.x;
        acc.y += v0.y + v1.y + v2.y + v3.y;
        acc.z += v0.z + v1.z + v2.z + v3.z;
        acc.w += v0.w + v1.w + v2.w + v3.w;
    }
    reinterpret_cast<float4*>(g_agg2)[(size_t)node * 16 + c] = acc;
}

// ---------------- fused tanh/FC (8 graphs/block, f32x2 accumulate) ---------
#define FC_CHUNKS 64
#define FC_KC ((NPG * H2) / FC_CHUNKS)  // 2048 k-elements per chunk
#define FC_GPB 8                        // graphs per block (Wfc L2 reuse)

__global__ void __launch_bounds__(256) k_fc(const float* __restrict__ Wfc,
                                            const float* __restrict__ b2,
                                            float* __restrict__ out) {
    __shared__ float sred[8][OUT_F];
    int chunk = blockIdx.x & (FC_CHUNKS - 1);
    int ggrp  = blockIdx.x >> 6;  // 0..3
    int t = threadIdx.x;
    int lane = t & 31, warp = t >> 5;
    int kbase = chunk * FC_KC;

    for (int gg = 0; gg < FC_GPB; gg++) {
        int g = ggrp * FC_GPB + gg;
        u64 acc2[OUT_F / 2];
#pragma unroll
        for (int o = 0; o < OUT_F / 2; o++) acc2[o] = 0ull;

#pragma unroll
        for (int i = 0; i < FC_KC / 256; i++) {
            int k = kbase + i * 256 + t;            // [0, 131072)
            int n = g * NPG + (k >> 6);
            int h = k & 63;
            float v = tanhx(fmaf(__ldg(&g_agg2[(size_t)g * (NPG * H2) + k]),
                                 g_dinv[n], __ldg(&b2[h])));
            u64 vp = pack2(v, v);
            const u64* w2 = reinterpret_cast<const u64*>(Wfc + (size_t)k * OUT_F);
#pragma unroll
            for (int o = 0; o < OUT_F / 2; o++) {
                u64 w = __ldg(&w2[o]);
                fma2(acc2[o], vp, w);
            }
        }

        float acc[OUT_F];
#pragma unroll
        for (int o = 0; o < OUT_F / 2; o++)
            unpack2(acc[2 * o], acc[2 * o + 1], acc2[o]);

#pragma unroll
        for (int o = 0; o < OUT_F; o++) {
            float s = acc[o];
#pragma unroll
            for (int off = 16; off > 0; off >>= 1)
                s += __shfl_down_sync(0xffffffffu, s, off);
            if (lane == 0) sred[warp][o] = s;
        }
        __syncthreads();
        if (t < OUT_F) {
            float s = 0.f;
#pragma unroll
            for (int w = 0; w < 8; w++) s += sred[w][t];
            atomicAdd(&out[g * OUT_F + t], s);
        }
        __syncthreads();
    }
}

// ---------------- launcher -------------------------------------------------
extern "C" void kernel_launch(void* const* d_in, const int* in_sizes, int n_in,
                              void* d_out, int out_size) {
    (void)in_sizes; (void)n_in; (void)out_size;
    const float* x   = (const float*)d_in[0];
    const int*   ei  = (const int*)d_in[1];
    // d_in[2] = batch (unused: layout is a fixed reshape)
    const float* W1  = (const float*)d_in[3];
    const float* b1  = (const float*)d_in[4];
    const float* W2  = (const float*)d_in[5];
    const float* b2  = (const float*)d_in[6];
    const float* Wfc = (const float*)d_in[7];
    const float* bfc = (const float*)d_in[8];
    float* out = (float*)d_out;

    const int* src = ei;
    const int* dst = ei + N_EDGES;

    k_init<<<N_NODES / 256, 256>>>(bfc, out);
    k_scatter<<<N_EDGES / 4 / 256, 256>>>(src, dst);
    k_xs<<<N_NODES / 256, 256>>>(x);
    k_gather1<<<(N_NODES * 4) / 256, 256>>>();
    k_h12<<<N_NODES / 128, 128>>>(W1, b1, W2);
    k_gather2<<<(N_NODES * 16) / 256, 256>>>();
    k_fc<<<4 * FC_CHUNKS, 256>>>(Wfc, b2, out);
}